// round 10
// baseline (speedup 1.0000x reference)
#include <cuda_runtime.h>
#include <cuda_fp16.h>
#include <cstdint>

#define P       4096
#define MOUT    64
#define ITILE   128
#define TILES   (P / ITILE)      // 32
#define SPLITS  8
#define KSPLIT  (P / SPLITS)     // 512
#define KC      64               // k per chunk
#define NCHUNK  (KSPLIT / KC)    // 8
#define NT      256
#define EXP_NEG 0.36787907f      // expf(-1.000001f)

// ---------------- device scratch ----------------
__device__ float g_Dpart[SPLITS][P][MOUT];   // split partials (8 MB, L2-cycled)
__device__ int   g_cnt[SPLITS][P];
__device__ int   g_total;                    // sticky any-neighbor flag (replay-safe)
__device__ int   g_tilectr[TILES];           // self-resetting completion counters

// ---------------- helpers ----------------
__device__ __forceinline__ uint32_t smem_u32(const void* p) {
    uint32_t a;
    asm("{ .reg .u64 t; cvta.to.shared.u64 t, %1; cvt.u32.u64 %0, t; }" : "=r"(a) : "l"(p));
    return a;
}
// 128-B rows (64 halves), 8x16B chunks: chunk' = chunk ^ (row&7) -> conflict-free
__device__ __forceinline__ uint32_t swz(int row, int kbyte) {
    return (uint32_t)(row * 128) + (uint32_t)((((kbyte >> 4) ^ (row & 7)) << 4) | (kbyte & 15));
}
__device__ __forceinline__ void sts64(uint32_t addr, uint32_t x, uint32_t y) {
    asm volatile("st.shared.v2.b32 [%0], {%1, %2};" :: "r"(addr), "r"(x), "r"(y) : "memory");
}
__device__ __forceinline__ void ldsm4(uint32_t* r, uint32_t addr) {
    asm volatile("ldmatrix.sync.aligned.m8n8.x4.shared.b16 {%0,%1,%2,%3}, [%4];"
                 : "=r"(r[0]), "=r"(r[1]), "=r"(r[2]), "=r"(r[3]) : "r"(addr));
}
__device__ __forceinline__ void ldsm4t(uint32_t* r, uint32_t addr) {
    asm volatile("ldmatrix.sync.aligned.m8n8.x4.trans.shared.b16 {%0,%1,%2,%3}, [%4];"
                 : "=r"(r[0]), "=r"(r[1]), "=r"(r[2]), "=r"(r[3]) : "r"(addr));
}
__device__ __forceinline__ void mma16816(float* c, const uint32_t* a, const uint32_t* b) {
    asm volatile("mma.sync.aligned.m16n8k16.row.col.f32.f16.f16.f32 "
                 "{%0,%1,%2,%3}, {%4,%5,%6,%7}, {%8,%9}, {%0,%1,%2,%3};"
                 : "+f"(c[0]), "+f"(c[1]), "+f"(c[2]), "+f"(c[3])
                 : "r"(a[0]), "r"(a[1]), "r"(a[2]), "r"(a[3]), "r"(b[0]), "r"(b[1]));
}

// ---------------- single fused kernel ----------------
extern __shared__ __align__(16) char smem[];   // [A0 16K][A1 16K][B0 8K][B1 8K] = 48 KB

__global__ __launch_bounds__(NT, 2)
void social_fused(const float* __restrict__ hidden,
                  const int*   __restrict__ nei,
                  float*       __restrict__ out) {
    const int tid    = threadIdx.x;
    const int lane   = tid & 31;
    const int w      = tid >> 5;
    const int warp_m = w & 3;            // i-rows warp_m*32 .. +31
    const int warp_n = w >> 2;           // n-cols warp_n*32 .. +31
    const int split  = blockIdx.x;
    const int tile   = blockIdx.y;
    const int i0     = tile * ITILE;
    const int k0base = split * KSPLIT;

    const uint32_t sbase = smem_u32(smem);
    const uint32_t sA[2] = {sbase,         sbase + 16384};
    const uint32_t sB[2] = {sbase + 32768, sbase + 40960};

    // A-load mapping: thread owns i-rows (tid>>4)+16s, k-slice (tid&15)*4..+3
    const int row_t = tid >> 4;
    const int slice = tid & 15;

    float acc[2][4][4];
    #pragma unroll
    for (int a = 0; a < 2; ++a)
        #pragma unroll
        for (int b = 0; b < 4; ++b)
            #pragma unroll
            for (int c = 0; c < 4; ++c) acc[a][b][c] = 0.0f;
    int cnt[8];
    #pragma unroll
    for (int s = 0; s < 8; ++s) cnt[s] = 0;

    int4   va[8];
    float4 vb[4];

    auto load_chunk = [&](int c) {
        const int k0 = k0base + c * KC;
        #pragma unroll
        for (int s = 0; s < 8; ++s)
            va[s] = *reinterpret_cast<const int4*>(
                nei + (size_t)(i0 + row_t + 16 * s) * P + k0 + slice * 4);
        #pragma unroll
        for (int q = 0; q < 4; ++q) {
            int idx = q * NT + tid;
            int kr = idx >> 4, mq4 = (idx & 15) * 4;
            vb[q] = *reinterpret_cast<const float4*>(
                hidden + (size_t)(k0 + kr) * MOUT + mq4);    // L2-resident (1 MB)
        }
    };
    auto sts_chunk = [&](int b) {
        #pragma unroll
        for (int s = 0; s < 8; ++s) {                        // A: mask -> fp16 {0,1}
            int r = row_t + 16 * s;
            uint32_t h0 = (va[s].x > 0) ? 0x3C00u : 0u;
            uint32_t h1 = (va[s].y > 0) ? 0x3C00u : 0u;
            uint32_t h2 = (va[s].z > 0) ? 0x3C00u : 0u;
            uint32_t h3 = (va[s].w > 0) ? 0x3C00u : 0u;
            cnt[s] += (va[s].x > 0) + (va[s].y > 0) + (va[s].z > 0) + (va[s].w > 0);
            sts64(sA[b] + swz(r, slice * 8), h0 | (h1 << 16), h2 | (h3 << 16));
        }
        #pragma unroll
        for (int q = 0; q < 4; ++q) {                        // B: fp32 -> fp16, K-major
            int idx = q * NT + tid;
            int kr = idx >> 4, mq4 = (idx & 15) * 4;
            __half2 h01 = __floats2half2_rn(vb[q].x, vb[q].y);
            __half2 h23 = __floats2half2_rn(vb[q].z, vb[q].w);
            sts64(sB[b] + swz(kr, mq4 * 2),
                  *reinterpret_cast<uint32_t*>(&h01), *reinterpret_cast<uint32_t*>(&h23));
        }
    };

    load_chunk(0);
    sts_chunk(0);
    __syncthreads();

    #pragma unroll 1
    for (int c = 0; c < NCHUNK; ++c) {
        const int b  = c & 1;
        const int nb = b ^ 1;
        if (c + 1 < NCHUNK) load_chunk(c + 1);

        #pragma unroll
        for (int k16 = 0; k16 < KC / 16; ++k16) {
            uint32_t afr[2][4];
            #pragma unroll
            for (int mt = 0; mt < 2; ++mt) {
                int row = warp_m * 32 + mt * 16 + (lane & 15);
                int kb  = k16 * 32 + ((lane >> 4) << 4);
                ldsm4(afr[mt], sA[b] + swz(row, kb));
            }
            uint32_t bfr[2][4];
            #pragma unroll
            for (int g = 0; g < 2; ++g) {      // trans-load from [k][m] smem
                int krow = k16 * 16 + (lane & 15);
                int mb   = warp_n * 32 + g * 16 + ((lane >> 4) << 3);
                ldsm4t(bfr[g], sB[b] + swz(krow, mb * 2));
            }
            #pragma unroll
            for (int mt = 0; mt < 2; ++mt)
                #pragma unroll
                for (int g = 0; g < 2; ++g) {
                    mma16816(acc[mt][2 * g],     afr[mt], &bfr[g][0]);  // n +0..7
                    mma16816(acc[mt][2 * g + 1], afr[mt], &bfr[g][2]);  // n +8..15
                }
        }

        if (c + 1 < NCHUNK) sts_chunk(nb);
        __syncthreads();
    }

    // ---- counts: reduce over the 16 lanes sharing each row; plain stores
    int any = 0;
    #pragma unroll
    for (int s = 0; s < 8; ++s) {
        int v = cnt[s];
        v += __shfl_xor_sync(0xffffffffu, v, 1);
        v += __shfl_xor_sync(0xffffffffu, v, 2);
        v += __shfl_xor_sync(0xffffffffu, v, 4);
        v += __shfl_xor_sync(0xffffffffu, v, 8);
        if ((lane & 15) == 0) {
            g_cnt[split][i0 + row_t + 16 * s] = v;
            any |= v;
        }
    }
    if ((lane & 15) == 0 && any) atomicOr(&g_total, 1);     // idempotent, replay-safe

    // ---- write split partials
    #pragma unroll
    for (int mt = 0; mt < 2; ++mt) {
        int ibase = i0 + warp_m * 32 + mt * 16 + (lane >> 2);
        #pragma unroll
        for (int g = 0; g < 2; ++g)
            #pragma unroll
            for (int t = 0; t < 2; ++t) {
                int n0 = warp_n * 32 + g * 16 + t * 8 + 2 * (lane & 3);
                const float* cfr = acc[mt][2 * g + t];
                *reinterpret_cast<float2*>(&g_Dpart[split][ibase][n0]) =
                    make_float2(cfr[0], cfr[1]);
                *reinterpret_cast<float2*>(&g_Dpart[split][ibase + 8][n0]) =
                    make_float2(cfr[2], cfr[3]);
            }
    }

    // ---- completion protocol (threadfence-reduction pattern)
    __threadfence();
    __syncthreads();
    __shared__ int s_last;
    if (tid == 0) s_last = atomicAdd(&g_tilectr[tile], 1);
    __syncthreads();
    if (s_last != SPLITS - 1) return;

    // ---- last CTA of this i-tile: combine splits + analytic softmax scale
    __threadfence();
    const int gt = g_total;
    #pragma unroll
    for (int rr = 0; rr < 4; ++rr) {
        int loc = (rr * NT + tid) * 8;          // 0..8191 within tile
        int i   = i0 + (loc >> 6);
        int col = loc & 63;
        if (gt > 0) {
            float4 s0 = make_float4(0.f, 0.f, 0.f, 0.f), s1 = s0;
            #pragma unroll
            for (int sp = 0; sp < SPLITS; ++sp) {
                float4 a4 = *reinterpret_cast<const float4*>(&g_Dpart[sp][i][col]);
                float4 b4 = *reinterpret_cast<const float4*>(&g_Dpart[sp][i][col + 4]);
                s0.x += a4.x; s0.y += a4.y; s0.z += a4.z; s0.w += a4.w;
                s1.x += b4.x; s1.y += b4.y; s1.z += b4.z; s1.w += b4.w;
            }
            int csum = 0;
            #pragma unroll
            for (int sp = 0; sp < SPLITS; ++sp) csum += g_cnt[sp][i];
            float cn = (float)csum;
            float inv = 1.0f / (cn + ((float)P - cn) * EXP_NEG);
            s0.x *= inv; s0.y *= inv; s0.z *= inv; s0.w *= inv;
            s1.x *= inv; s1.y *= inv; s1.z *= inv; s1.w *= inv;
            *reinterpret_cast<float4*>(out + (size_t)i * MOUT + col)     = s0;
            *reinterpret_cast<float4*>(out + (size_t)i * MOUT + col + 4) = s1;
        } else {
            *reinterpret_cast<float4*>(out + (size_t)i * MOUT + col) =
                *reinterpret_cast<const float4*>(hidden + (size_t)i * MOUT + col);
            *reinterpret_cast<float4*>(out + (size_t)i * MOUT + col + 4) =
                *reinterpret_cast<const float4*>(hidden + (size_t)i * MOUT + col + 4);
        }
    }
    if (tid == 0) g_tilectr[tile] = 0;          // self-reset -> next graph replay sees 0
}

// ---------------- launch: ONE kernel ----------------
extern "C" void kernel_launch(void* const* d_in, const int* in_sizes, int n_in,
                              void* d_out, int out_size) {
    const float* hidden = (const float*)d_in[0];
    // d_in[1] (corr_index) is unused by the reference math — never read.
    const int*   nei    = (const int*)d_in[2];
    float*       out    = (float*)d_out;

    const int smem_bytes = 49152;   // 2x16K A + 2x8K B
    cudaFuncSetAttribute(social_fused,
                         cudaFuncAttributeMaxDynamicSharedMemorySize, smem_bytes);

    social_fused<<<dim3(SPLITS, TILES), NT, smem_bytes>>>(hidden, nei, out);
}

// round 11
// speedup vs baseline: 1.0801x; 1.0801x over previous
#include <cuda_runtime.h>
#include <cuda_fp16.h>
#include <cstdint>

#define P       4096
#define MOUT    64
#define ITILE   128
#define TILES   (P / ITILE)      // 32
#define SPLITS  8
#define KSPLIT  (P / SPLITS)     // 512
#define KC      64               // k per chunk
#define NCHUNK  (KSPLIT / KC)    // 8
#define NT      256
#define EXP_NEG 0.36787907f      // expf(-1.000001f)

// ---------------- device scratch ----------------
__device__ float g_Dpart[SPLITS][P][MOUT];   // split partials (8 MB)
__device__ int   g_cnt[SPLITS][P];
__device__ int   g_total;                    // sticky any-neighbor flag (replay-safe)
__device__ int   g_tilectr[TILES];           // self-resetting completion counters

// ---------------- helpers ----------------
__device__ __forceinline__ uint32_t smem_u32(const void* p) {
    uint32_t a;
    asm("{ .reg .u64 t; cvta.to.shared.u64 t, %1; cvt.u32.u64 %0, t; }" : "=r"(a) : "l"(p));
    return a;
}
// 128-B rows (64 halves), 8x16B chunks: chunk' = chunk ^ (row&7) -> conflict-free
__device__ __forceinline__ uint32_t swz(int row, int kbyte) {
    return (uint32_t)(row * 128) + (uint32_t)((((kbyte >> 4) ^ (row & 7)) << 4) | (kbyte & 15));
}
__device__ __forceinline__ void sts64(uint32_t addr, uint32_t x, uint32_t y) {
    asm volatile("st.shared.v2.b32 [%0], {%1, %2};" :: "r"(addr), "r"(x), "r"(y) : "memory");
}
__device__ __forceinline__ void ldsm4(uint32_t* r, uint32_t addr) {
    asm volatile("ldmatrix.sync.aligned.m8n8.x4.shared.b16 {%0,%1,%2,%3}, [%4];"
                 : "=r"(r[0]), "=r"(r[1]), "=r"(r[2]), "=r"(r[3]) : "r"(addr));
}
__device__ __forceinline__ void ldsm4t(uint32_t* r, uint32_t addr) {
    asm volatile("ldmatrix.sync.aligned.m8n8.x4.trans.shared.b16 {%0,%1,%2,%3}, [%4];"
                 : "=r"(r[0]), "=r"(r[1]), "=r"(r[2]), "=r"(r[3]) : "r"(addr));
}
__device__ __forceinline__ void mma16816(float* c, const uint32_t* a, const uint32_t* b) {
    asm volatile("mma.sync.aligned.m16n8k16.row.col.f32.f16.f16.f32 "
                 "{%0,%1,%2,%3}, {%4,%5,%6,%7}, {%8,%9}, {%0,%1,%2,%3};"
                 : "+f"(c[0]), "+f"(c[1]), "+f"(c[2]), "+f"(c[3])
                 : "r"(a[0]), "r"(a[1]), "r"(a[2]), "r"(a[3]), "r"(b[0]), "r"(b[1]));
}

// ---------------- single fused kernel ----------------
// smem: [A0 16K][A1 16K][B persistent 64K] = 96 KB
extern __shared__ __align__(16) char smem[];

__global__ __launch_bounds__(NT, 2)
void social_fused(const float* __restrict__ hidden,
                  const int*   __restrict__ nei,
                  float*       __restrict__ out) {
    const int tid    = threadIdx.x;
    const int lane   = tid & 31;
    const int w      = tid >> 5;
    const int warp_m = w & 3;            // i-rows warp_m*32 .. +31
    const int warp_n = w >> 2;           // n-cols warp_n*32 .. +31
    const int split  = blockIdx.x;
    const int tile   = blockIdx.y;
    const int i0     = tile * ITILE;
    const int k0base = split * KSPLIT;

    const uint32_t sbase = smem_u32(smem);
    const uint32_t sA[2] = {sbase, sbase + 16384};
    const uint32_t sBP   = sbase + 32768;          // persistent B: 512 k-rows x 128 B

    const int row_t = tid >> 4;          // A-load row within 16-row groups
    const int slice = tid & 15;          // A-load k-slice (x4 ints)

    float acc[2][4][4];
    #pragma unroll
    for (int a = 0; a < 2; ++a)
        #pragma unroll
        for (int b = 0; b < 4; ++b)
            #pragma unroll
            for (int c = 0; c < 4; ++c) acc[a][b][c] = 0.0f;
    int cnt[8];
    #pragma unroll
    for (int s = 0; s < 8; ++s) cnt[s] = 0;

    int4 va[8];

    // ---- one-time B init: hidden fp32 [k][m] -> persistent fp16 smem (K-major rows)
    #pragma unroll
    for (int cc = 0; cc < NCHUNK; ++cc) {
        const int k0 = k0base + cc * KC;
        #pragma unroll
        for (int q = 0; q < 4; ++q) {
            int idx = q * NT + tid;
            int kr = idx >> 4, mq4 = (idx & 15) * 4;
            float4 v = *reinterpret_cast<const float4*>(
                hidden + (size_t)(k0 + kr) * MOUT + mq4);        // L2-resident (1 MB)
            __half2 h01 = __floats2half2_rn(v.x, v.y);
            __half2 h23 = __floats2half2_rn(v.z, v.w);
            sts64(sBP + swz(cc * KC + kr, mq4 * 2),
                  *reinterpret_cast<uint32_t*>(&h01), *reinterpret_cast<uint32_t*>(&h23));
        }
    }

    auto load_A = [&](int c) {
        const int k0 = k0base + c * KC;
        #pragma unroll
        for (int s = 0; s < 8; ++s)
            va[s] = *reinterpret_cast<const int4*>(
                nei + (size_t)(i0 + row_t + 16 * s) * P + k0 + slice * 4);
    };
    auto sts_A = [&](int b) {
        #pragma unroll
        for (int s = 0; s < 8; ++s) {
            int r = row_t + 16 * s;
            uint32_t h0 = (va[s].x > 0) ? 0x3C00u : 0u;
            uint32_t h1 = (va[s].y > 0) ? 0x3C00u : 0u;
            uint32_t h2 = (va[s].z > 0) ? 0x3C00u : 0u;
            uint32_t h3 = (va[s].w > 0) ? 0x3C00u : 0u;
            cnt[s] += (va[s].x > 0) + (va[s].y > 0) + (va[s].z > 0) + (va[s].w > 0);
            sts64(sA[b] + swz(r, slice * 8), h0 | (h1 << 16), h2 | (h3 << 16));
        }
    };

    load_A(0);
    sts_A(0);
    __syncthreads();                     // covers B init + A(0)

    #pragma unroll 1
    for (int c = 0; c < NCHUNK; ++c) {
        const int b  = c & 1;
        const int nb = b ^ 1;
        if (c + 1 < NCHUNK) load_A(c + 1);

        #pragma unroll
        for (int k16 = 0; k16 < KC / 16; ++k16) {
            uint32_t afr[2][4];
            #pragma unroll
            for (int mt = 0; mt < 2; ++mt) {
                int row = warp_m * 32 + mt * 16 + (lane & 15);
                int kb  = k16 * 32 + ((lane >> 4) << 4);
                ldsm4(afr[mt], sA[b] + swz(row, kb));
            }
            uint32_t bfr[2][4];
            #pragma unroll
            for (int g = 0; g < 2; ++g) {          // trans-load from persistent [k][m]
                int krow = c * KC + k16 * 16 + (lane & 15);
                int mb   = warp_n * 32 + g * 16 + ((lane >> 4) << 3);
                ldsm4t(bfr[g], sBP + swz(krow, mb * 2));
            }
            #pragma unroll
            for (int mt = 0; mt < 2; ++mt)
                #pragma unroll
                for (int g = 0; g < 2; ++g) {
                    mma16816(acc[mt][2 * g],     afr[mt], &bfr[g][0]);  // n +0..7
                    mma16816(acc[mt][2 * g + 1], afr[mt], &bfr[g][2]);  // n +8..15
                }
        }

        if (c + 1 < NCHUNK) sts_A(nb);
        __syncthreads();
    }

    // ---- counts: reduce over the 16 lanes sharing each row; plain stores
    int any = 0;
    #pragma unroll
    for (int s = 0; s < 8; ++s) {
        int v = cnt[s];
        v += __shfl_xor_sync(0xffffffffu, v, 1);
        v += __shfl_xor_sync(0xffffffffu, v, 2);
        v += __shfl_xor_sync(0xffffffffu, v, 4);
        v += __shfl_xor_sync(0xffffffffu, v, 8);
        if ((lane & 15) == 0) {
            g_cnt[split][i0 + row_t + 16 * s] = v;
            any |= v;
        }
    }
    if ((lane & 15) == 0 && any) atomicOr(&g_total, 1);     // idempotent, replay-safe

    // ---- write split partials
    #pragma unroll
    for (int mt = 0; mt < 2; ++mt) {
        int ibase = i0 + warp_m * 32 + mt * 16 + (lane >> 2);
        #pragma unroll
        for (int g = 0; g < 2; ++g)
            #pragma unroll
            for (int t = 0; t < 2; ++t) {
                int n0 = warp_n * 32 + g * 16 + t * 8 + 2 * (lane & 3);
                const float* cfr = acc[mt][2 * g + t];
                *reinterpret_cast<float2*>(&g_Dpart[split][ibase][n0]) =
                    make_float2(cfr[0], cfr[1]);
                *reinterpret_cast<float2*>(&g_Dpart[split][ibase + 8][n0]) =
                    make_float2(cfr[2], cfr[3]);
            }
    }

    // ---- completion protocol (threadfence-reduction pattern)
    __threadfence();
    __syncthreads();
    __shared__ int s_last;
    if (tid == 0) s_last = atomicAdd(&g_tilectr[tile], 1);
    __syncthreads();
    if (s_last != SPLITS - 1) return;

    // ---- last CTA of this i-tile: combine splits + analytic softmax scale
    __threadfence();
    const int gt = g_total;
    #pragma unroll
    for (int rr = 0; rr < 4; ++rr) {
        int loc = (rr * NT + tid) * 8;          // 0..8191 within tile
        int i   = i0 + (loc >> 6);
        int col = loc & 63;
        if (gt > 0) {
            float4 s0 = make_float4(0.f, 0.f, 0.f, 0.f), s1 = s0;
            #pragma unroll
            for (int sp = 0; sp < SPLITS; ++sp) {
                float4 a4 = *reinterpret_cast<const float4*>(&g_Dpart[sp][i][col]);
                float4 b4 = *reinterpret_cast<const float4*>(&g_Dpart[sp][i][col + 4]);
                s0.x += a4.x; s0.y += a4.y; s0.z += a4.z; s0.w += a4.w;
                s1.x += b4.x; s1.y += b4.y; s1.z += b4.z; s1.w += b4.w;
            }
            int csum = 0;
            #pragma unroll
            for (int sp = 0; sp < SPLITS; ++sp) csum += g_cnt[sp][i];
            float cn = (float)csum;
            float inv = 1.0f / (cn + ((float)P - cn) * EXP_NEG);
            s0.x *= inv; s0.y *= inv; s0.z *= inv; s0.w *= inv;
            s1.x *= inv; s1.y *= inv; s1.z *= inv; s1.w *= inv;
            *reinterpret_cast<float4*>(out + (size_t)i * MOUT + col)     = s0;
            *reinterpret_cast<float4*>(out + (size_t)i * MOUT + col + 4) = s1;
        } else {
            *reinterpret_cast<float4*>(out + (size_t)i * MOUT + col) =
                *reinterpret_cast<const float4*>(hidden + (size_t)i * MOUT + col);
            *reinterpret_cast<float4*>(out + (size_t)i * MOUT + col + 4) =
                *reinterpret_cast<const float4*>(hidden + (size_t)i * MOUT + col + 4);
        }
    }
    if (tid == 0) g_tilectr[tile] = 0;          // self-reset -> next graph replay sees 0
}

// ---------------- launch: ONE kernel ----------------
extern "C" void kernel_launch(void* const* d_in, const int* in_sizes, int n_in,
                              void* d_out, int out_size) {
    const float* hidden = (const float*)d_in[0];
    // d_in[1] (corr_index) is unused by the reference math — never read.
    const int*   nei    = (const int*)d_in[2];
    float*       out    = (float*)d_out;

    const int smem_bytes = 98304;   // 2x16K A + 64K persistent B
    cudaFuncSetAttribute(social_fused,
                         cudaFuncAttributeMaxDynamicSharedMemorySize, smem_bytes);

    social_fused<<<dim3(SPLITS, TILES), NT, smem_bytes>>>(hidden, nei, out);
}